// round 5
// baseline (speedup 1.0000x reference)
#include <cuda_runtime.h>
#include <cuda_bf16.h>

#define VOCAB 50000
#define D 256
#define E 20000
#define L 20

// ---------------- scratch (static device globals; no allocation) ----------------
__device__ float g_qemb[D];
__device__ float g_g0[D];        // alpha(d) * qemb[d]
__device__ float g_g1[D];        // beta(d)  * qemb[d]
__device__ float g_u[VOCAB];
__device__ float g_w[VOCAB];
__device__ float g_A[VOCAB];     // unnormalized attention mass per vocab id
__device__ float g_B[VOCAB];     // same, weighted by l/L
__device__ float g_accA[D];
__device__ float g_accB[D];
__device__ float g_wte1[D];
__device__ float g_sumw;         // sum of exp(scores)
__device__ float g_sumexp;       // sum of exp(logits)

__device__ __forceinline__ float warp_sum(float v) {
    #pragma unroll
    for (int o = 16; o > 0; o >>= 1) v += __shfl_xor_sync(0xffffffffu, v, o);
    return v;
}

__device__ __forceinline__ float dot8(float4 x0, float4 x1, float4 c0, float4 c1) {
    return x0.x*c0.x + x0.y*c0.y + x0.z*c0.z + x0.w*c0.w
         + x1.x*c1.x + x1.y*c1.y + x1.z*c1.z + x1.w*c1.w;
}

// ---------------- K1: q_emb + derived vectors, zero accumulators ----------------
__global__ void k1_qemb(const int* __restrict__ question,
                        const float* __restrict__ q_table) {
    int d = threadIdx.x;                         // 256 threads
    float a  = 1.0f - (float)d * (1.0f / D);
    float be = 2.0f * (float)d * (1.0f / D) - 1.0f;
    float s = 0.0f;
    #pragma unroll
    for (int l = 0; l < L; ++l) {
        int v = question[l];
        float pe = a + ((float)l * (1.0f / L)) * be;
        s += __ldg(&q_table[(size_t)v * D + d]) * pe;
    }
    g_qemb[d] = s;
    g_g0[d] = a * s;
    g_g1[d] = be * s;
    g_accA[d] = 0.0f; g_accB[d] = 0.0f; g_wte1[d] = 0.0f;
    if (d == 0) { g_sumw = 0.0f; g_sumexp = 0.0f; }
}

// ---------------- K2: u[v], w[v] over q_table; zero A/B --------------------------
// 5 rows per warp (batched loads for MLP), 8 warps -> 40 rows/block, 1250 blocks
#define K2_RPW 5
__global__ void k2_uw(const float* __restrict__ q_table) {
    __shared__ float4 s0[64], s1[64];
    int t = threadIdx.x;
    if (t < 64) {
        s0[t] = ((const float4*)g_g0)[t];
        s1[t] = ((const float4*)g_g1)[t];
    }
    __syncthreads();
    int warp = t >> 5, lane = t & 31;
    int vbase = blockIdx.x * (8 * K2_RPW) + warp * K2_RPW;
    float4 c0 = s0[lane], c1 = s0[lane + 32];
    float4 d0 = s1[lane], d1 = s1[lane + 32];
    float u[K2_RPW], w[K2_RPW];
    #pragma unroll
    for (int r = 0; r < K2_RPW; ++r) {
        const float4* row = (const float4*)(q_table + (size_t)(vbase + r) * D);
        float4 x0 = __ldg(&row[lane]);
        float4 x1 = __ldg(&row[lane + 32]);
        u[r] = dot8(x0, x1, c0, c1);
        w[r] = dot8(x0, x1, d0, d1);
    }
    #pragma unroll
    for (int r = 0; r < K2_RPW; ++r) { u[r] = warp_sum(u[r]); w[r] = warp_sum(w[r]); }
    if (lane == 0) {
        #pragma unroll
        for (int r = 0; r < K2_RPW; ++r) { g_u[vbase + r] = u[r]; g_w[vbase + r] = w[r]; }
    }
    if (lane < K2_RPW) { g_A[vbase + lane] = 0.0f; g_B[vbase + lane] = 0.0f; }
}

// ---------------- K34: fused scores + exp + A/B scatter + weights@te1 ------------
// chunk of 32 evidences per block, 625 blocks. |scores| tiny (tables *0.05)
// -> exp without max-shift is exact. Normalization deferred to K6.
#define K34_CHUNK  32
#define K34_BLOCKS (E / K34_CHUNK)    // 625
__global__ void k34_weights(const int* __restrict__ evidence,
                            const float* __restrict__ te2,
                            const float* __restrict__ te1) {
    __shared__ float4 sq[64];
    __shared__ float s_w[K34_CHUNK];
    int t = threadIdx.x;                      // 256
    int warp = t >> 5, lane = t & 31;
    if (t < 64) sq[t] = ((const float4*)g_qemb)[t];
    __syncthreads();
    int e0 = blockIdx.x * K34_CHUNK;
    float4 q0 = sq[lane], q1 = sq[lane + 32];
    float part[4];
    #pragma unroll
    for (int r = 0; r < 4; ++r) {
        int e = e0 + warp * 4 + r;
        float p = 0.0f;
        if (lane < L) {
            int v = __ldg(&evidence[e * L + lane]);
            p = g_u[v] + ((float)lane * (1.0f / L)) * g_w[v];
        }
        const float4* row = (const float4*)(te2 + (size_t)e * D);
        float4 x0 = __ldg(&row[lane]);
        float4 x1 = __ldg(&row[lane + 32]);
        part[r] = p + dot8(x0, x1, q0, q1);
    }
    #pragma unroll
    for (int r = 0; r < 4; ++r) part[r] = warp_sum(part[r]);
    if (lane == 0) {
        #pragma unroll
        for (int r = 0; r < 4; ++r) s_w[warp * 4 + r] = part[r];
    }
    __syncthreads();
    // exp + block sum (single warp), then scatter
    if (t < 32) {
        float w = expf(s_w[t]);
        s_w[t] = w;
        float s = warp_sum(w);
        if (t == 0) atomicAdd(&g_sumw, s);
    }
    __syncthreads();
    for (int i = t; i < K34_CHUNK * L; i += 256) {
        int el = i / L;
        int l  = i - el * L;
        int v  = __ldg(&evidence[(e0 + el) * L + l]);
        float w = s_w[el];
        atomicAdd(&g_A[v], w);
        atomicAdd(&g_B[v], w * ((float)l * (1.0f / L)));
    }
    // wte1[d] += sum_e w_e * te1[e, d]  (unnormalized)
    int d = t;
    float acc = 0.0f;
    #pragma unroll 8
    for (int el = 0; el < K34_CHUNK; ++el)
        acc += s_w[el] * __ldg(&te1[(size_t)(e0 + el) * D + d]);
    atomicAdd(&g_wte1[d], acc);
}

// ---------------- K5: accA/accB = A@e_table, B@e_table ---------------------------
// float4 loads, 4 row-groups per block, 40 rows/block, 1250 blocks
#define K5_BLOCKS 1250
#define K5_ROWS   40
__global__ void k5_etable(const float* __restrict__ e_table) {
    __shared__ float4 s_a[4][64];
    __shared__ float4 s_b[4][64];
    int t = threadIdx.x;                      // 256
    int d4 = t & 63;                          // float4 column index (4 floats)
    int r  = t >> 6;                          // row group 0..3
    int v0 = blockIdx.x * K5_ROWS;
    const float4* ev = (const float4*)e_table;
    float4 a = make_float4(0.f, 0.f, 0.f, 0.f);
    float4 b = make_float4(0.f, 0.f, 0.f, 0.f);
    #pragma unroll
    for (int i = 0; i < K5_ROWS / 4; ++i) {   // 10 iterations, fully unrolled
        int v = v0 + i * 4 + r;
        float Av = g_A[v], Bv = g_B[v];
        float4 x = __ldg(&ev[(size_t)v * (D / 4) + d4]);
        a.x += Av * x.x; a.y += Av * x.y; a.z += Av * x.z; a.w += Av * x.w;
        b.x += Bv * x.x; b.y += Bv * x.y; b.z += Bv * x.z; b.w += Bv * x.w;
    }
    s_a[r][d4] = a; s_b[r][d4] = b;
    __syncthreads();
    if (r == 0) {
        float4 a1 = s_a[1][d4], a2 = s_a[2][d4], a3 = s_a[3][d4];
        float4 b1 = s_b[1][d4], b2 = s_b[2][d4], b3 = s_b[3][d4];
        a.x += a1.x + a2.x + a3.x; a.y += a1.y + a2.y + a3.y;
        a.z += a1.z + a2.z + a3.z; a.w += a1.w + a2.w + a3.w;
        b.x += b1.x + b2.x + b3.x; b.y += b1.y + b2.y + b3.y;
        b.z += b1.z + b2.z + b3.z; b.w += b1.w + b2.w + b3.w;
        int d = d4 * 4;
        atomicAdd(&g_accA[d + 0], a.x); atomicAdd(&g_accA[d + 1], a.y);
        atomicAdd(&g_accA[d + 2], a.z); atomicAdd(&g_accA[d + 3], a.w);
        atomicAdd(&g_accB[d + 0], b.x); atomicAdd(&g_accB[d + 1], b.y);
        atomicAdd(&g_accB[d + 2], b.z); atomicAdd(&g_accB[d + 3], b.w);
    }
}

// ---------------- K6: logits + exp + block-aggregated sumexp ---------------------
// 1024 threads, 4 rows per warp -> 128 rows/block. Each block recomputes
// feat[256] (folds 1/sumw). |logits| tiny -> exp without max-shift exact.
__global__ void __launch_bounds__(1024)
k6_logits(const float* __restrict__ W, const float* __restrict__ b,
          float* __restrict__ out) {
    __shared__ float s_feat[D];
    __shared__ float s_p[32];
    int t = threadIdx.x;
    if (t < D) {
        float a  = 1.0f - (float)t * (1.0f / D);
        float be = 2.0f * (float)t * (1.0f / D) - 1.0f;
        float invS = 1.0f / g_sumw;
        s_feat[t] = (a * g_accA[t] + be * g_accB[t] + g_wte1[t]) * invS + g_qemb[t];
    }
    __syncthreads();
    int warp = t >> 5, lane = t & 31;
    int vbase = blockIdx.x * 128 + warp * 4;
    const float4* sf = (const float4*)s_feat;
    float4 f0 = sf[lane], f1 = sf[lane + 32];
    float s[4];
    #pragma unroll
    for (int r = 0; r < 4; ++r) {
        int v = vbase + r;
        s[r] = 0.0f;
        if (v < VOCAB) {
            const float4* row = (const float4*)(W + (size_t)v * D);
            float4 x0 = __ldg(&row[lane]);
            float4 x1 = __ldg(&row[lane + 32]);
            s[r] = dot8(x0, x1, f0, f1);
        }
    }
    #pragma unroll
    for (int r = 0; r < 4; ++r) s[r] = warp_sum(s[r]);
    float p_sum = 0.0f;
    if (lane == 0) {
        #pragma unroll
        for (int r = 0; r < 4; ++r) {
            int v = vbase + r;
            if (v < VOCAB) {
                float p = expf(s[r] + __ldg(&b[v]));
                out[v] = p;                  // unnormalized
                p_sum += p;
            }
        }
        s_p[warp] = p_sum;
    }
    __syncthreads();
    if (t < 32) {
        float x = s_p[t];
        x = warp_sum(x);
        if (t == 0) atomicAdd(&g_sumexp, x);
    }
}

// ---------------- K7: normalize output -------------------------------------------
__global__ void k7_scale(float* __restrict__ out) {
    int i = blockIdx.x * blockDim.x + threadIdx.x;
    float inv = 1.0f / g_sumexp;
    if (i < VOCAB) out[i] *= inv;
}

// ---------------- launch ---------------------------------------------------------
extern "C" void kernel_launch(void* const* d_in, const int* in_sizes, int n_in,
                              void* d_out, int out_size) {
    const int*   evidence = (const int*)  d_in[0];
    const int*   question = (const int*)  d_in[1];
    const float* q_table  = (const float*)d_in[2];
    const float* e_table  = (const float*)d_in[3];
    const float* te1      = (const float*)d_in[4];
    const float* te2      = (const float*)d_in[5];
    const float* W        = (const float*)d_in[6];
    const float* b        = (const float*)d_in[7];
    float* out = (float*)d_out;

    k1_qemb<<<1, 256>>>(question, q_table);
    k2_uw<<<VOCAB / 40, 256>>>(q_table);
    k34_weights<<<K34_BLOCKS, 256>>>(evidence, te2, te1);
    k5_etable<<<K5_BLOCKS, 256>>>(e_table);
    k6_logits<<<(VOCAB + 127) / 128, 1024>>>(W, b, out);
    k7_scale<<<(VOCAB + 255) / 256, 256>>>(out);
}

// round 6
// speedup vs baseline: 1.0698x; 1.0698x over previous
#include <cuda_runtime.h>
#include <cuda_bf16.h>

#define VOCAB 50000
#define D 256
#define E 20000
#define L 20

// ---------------- scratch (static device globals; no allocation) ----------------
__device__ float g_qemb[D];
__device__ float g_g0[D];        // alpha(d) * qemb[d]
__device__ float g_g1[D];        // beta(d)  * qemb[d]
__device__ float g_u[VOCAB];
__device__ float g_w[VOCAB];
__device__ float g_A[VOCAB];     // unnormalized attention mass per vocab id
__device__ float g_B[VOCAB];     // same, weighted by l/L
__device__ float g_accA[D];
__device__ float g_accB[D];
__device__ float g_wte1[D];
__device__ float g_sumw;         // sum of exp(scores)
__device__ float g_sumexp;       // sum of exp(logits)

__device__ __forceinline__ float warp_sum(float v) {
    #pragma unroll
    for (int o = 16; o > 0; o >>= 1) v += __shfl_xor_sync(0xffffffffu, v, o);
    return v;
}

__device__ __forceinline__ float dot8(float4 x0, float4 x1, float4 c0, float4 c1) {
    return x0.x*c0.x + x0.y*c0.y + x0.z*c0.z + x0.w*c0.w
         + x1.x*c1.x + x1.y*c1.y + x1.z*c1.z + x1.w*c1.w;
}

// ---------------- K1: q_emb + derived vectors, zero accumulators ----------------
__global__ void k1_qemb(const int* __restrict__ question,
                        const float* __restrict__ q_table) {
    int d = threadIdx.x;                         // 256 threads
    float a  = 1.0f - (float)d * (1.0f / D);
    float be = 2.0f * (float)d * (1.0f / D) - 1.0f;
    float s = 0.0f;
    #pragma unroll
    for (int l = 0; l < L; ++l) {
        int v = question[l];
        float pe = a + ((float)l * (1.0f / L)) * be;
        s += __ldg(&q_table[(size_t)v * D + d]) * pe;
    }
    g_qemb[d] = s;
    g_g0[d] = a * s;
    g_g1[d] = be * s;
    g_accA[d] = 0.0f; g_accB[d] = 0.0f; g_wte1[d] = 0.0f;
    if (d == 0) { g_sumw = 0.0f; g_sumexp = 0.0f; }
}

// ---------------- K2: u[v], w[v] over q_table; zero A/B --------------------------
// 5 rows per warp (batched float4 loads), 8 warps -> 40 rows/block, 1250 blocks
#define K2_RPW 5
__global__ void __launch_bounds__(256, 2)
k2_uw(const float* __restrict__ q_table) {
    __shared__ float4 s0[64], s1[64];
    int t = threadIdx.x;
    if (t < 64) {
        s0[t] = ((const float4*)g_g0)[t];
        s1[t] = ((const float4*)g_g1)[t];
    }
    __syncthreads();
    int warp = t >> 5, lane = t & 31;
    int vbase = blockIdx.x * (8 * K2_RPW) + warp * K2_RPW;
    float4 c0 = s0[lane], c1 = s0[lane + 32];
    float4 d0 = s1[lane], d1 = s1[lane + 32];
    float4 x0[K2_RPW], x1[K2_RPW];
    #pragma unroll
    for (int r = 0; r < K2_RPW; ++r) {
        const float4* row = (const float4*)(q_table + (size_t)(vbase + r) * D);
        x0[r] = __ldg(&row[lane]);
        x1[r] = __ldg(&row[lane + 32]);
    }
    float u[K2_RPW], w[K2_RPW];
    #pragma unroll
    for (int r = 0; r < K2_RPW; ++r) {
        u[r] = dot8(x0[r], x1[r], c0, c1);
        w[r] = dot8(x0[r], x1[r], d0, d1);
    }
    #pragma unroll
    for (int r = 0; r < K2_RPW; ++r) { u[r] = warp_sum(u[r]); w[r] = warp_sum(w[r]); }
    if (lane == 0) {
        #pragma unroll
        for (int r = 0; r < K2_RPW; ++r) { g_u[vbase + r] = u[r]; g_w[vbase + r] = w[r]; }
    }
    if (lane < K2_RPW) { g_A[vbase + lane] = 0.0f; g_B[vbase + lane] = 0.0f; }
}

// ---------------- K34: fused scores + exp + A/B scatter + weights@te1 ------------
// chunk of 32 evidences per block, 625 blocks. |scores| tiny (tables *0.05)
// -> exp without max-shift is exact. Normalization deferred to K6.
#define K34_CHUNK  32
#define K34_BLOCKS (E / K34_CHUNK)    // 625
__global__ void __launch_bounds__(256, 2)
k34_weights(const int* __restrict__ evidence,
            const float* __restrict__ te2,
            const float* __restrict__ te1) {
    __shared__ float4 sq[64];
    __shared__ float s_w[K34_CHUNK];
    int t = threadIdx.x;                      // 256
    int warp = t >> 5, lane = t & 31;
    if (t < 64) sq[t] = ((const float4*)g_qemb)[t];
    __syncthreads();
    int e0 = blockIdx.x * K34_CHUNK;
    float4 q0 = sq[lane], q1 = sq[lane + 32];
    float4 x0[4], x1[4];
    #pragma unroll
    for (int r = 0; r < 4; ++r) {
        const float4* row = (const float4*)(te2 + (size_t)(e0 + warp * 4 + r) * D);
        x0[r] = __ldg(&row[lane]);
        x1[r] = __ldg(&row[lane + 32]);
    }
    float part[4];
    #pragma unroll
    for (int r = 0; r < 4; ++r) {
        int e = e0 + warp * 4 + r;
        float p = 0.0f;
        if (lane < L) {
            int v = __ldg(&evidence[e * L + lane]);
            p = g_u[v] + ((float)lane * (1.0f / L)) * g_w[v];
        }
        part[r] = p + dot8(x0[r], x1[r], q0, q1);
    }
    #pragma unroll
    for (int r = 0; r < 4; ++r) part[r] = warp_sum(part[r]);
    if (lane == 0) {
        #pragma unroll
        for (int r = 0; r < 4; ++r) s_w[warp * 4 + r] = part[r];
    }
    __syncthreads();
    // exp + block sum (single warp), then scatter
    if (t < 32) {
        float w = expf(s_w[t]);
        s_w[t] = w;
        float s = warp_sum(w);
        if (t == 0) atomicAdd(&g_sumw, s);
    }
    __syncthreads();
    for (int i = t; i < K34_CHUNK * L; i += 256) {
        int el = i / L;
        int l  = i - el * L;
        int v  = __ldg(&evidence[(e0 + el) * L + l]);
        float w = s_w[el];
        atomicAdd(&g_A[v], w);
        atomicAdd(&g_B[v], w * ((float)l * (1.0f / L)));
    }
    // wte1[d] += sum_e w_e * te1[e, d]  (unnormalized)
    int d = t;
    float acc = 0.0f;
    #pragma unroll 8
    for (int el = 0; el < K34_CHUNK; ++el)
        acc += s_w[el] * __ldg(&te1[(size_t)(e0 + el) * D + d]);
    atomicAdd(&g_wte1[d], acc);
}

// ---------------- K5: accA/accB = A@e_table, B@e_table ---------------------------
// float4 loads, 4 row-groups per block, 40 rows/block, 1250 blocks.
// launch_bounds(256,2) -> up to 128 regs so all 10 float4 loads stay in flight.
#define K5_BLOCKS 1250
#define K5_ROWS   40
__global__ void __launch_bounds__(256, 2)
k5_etable(const float* __restrict__ e_table) {
    __shared__ float4 s_a[4][64];
    __shared__ float4 s_b[4][64];
    int t = threadIdx.x;                      // 256
    int d4 = t & 63;                          // float4 column index
    int r  = t >> 6;                          // row group 0..3
    int v0 = blockIdx.x * K5_ROWS;
    const float4* ev = (const float4*)e_table;
    // batch all 10 row loads + A/B coefficients up front for max MLP
    float4 x[K5_ROWS / 4];
    float Av[K5_ROWS / 4], Bv[K5_ROWS / 4];
    #pragma unroll
    for (int i = 0; i < K5_ROWS / 4; ++i) {
        int v = v0 + i * 4 + r;
        x[i]  = __ldg(&ev[(size_t)v * (D / 4) + d4]);
        Av[i] = __ldg(&g_A[v]);
        Bv[i] = __ldg(&g_B[v]);
    }
    float4 a = make_float4(0.f, 0.f, 0.f, 0.f);
    float4 b = make_float4(0.f, 0.f, 0.f, 0.f);
    #pragma unroll
    for (int i = 0; i < K5_ROWS / 4; ++i) {
        a.x += Av[i] * x[i].x; a.y += Av[i] * x[i].y;
        a.z += Av[i] * x[i].z; a.w += Av[i] * x[i].w;
        b.x += Bv[i] * x[i].x; b.y += Bv[i] * x[i].y;
        b.z += Bv[i] * x[i].z; b.w += Bv[i] * x[i].w;
    }
    s_a[r][d4] = a; s_b[r][d4] = b;
    __syncthreads();
    if (r == 0) {
        float4 a1 = s_a[1][d4], a2 = s_a[2][d4], a3 = s_a[3][d4];
        float4 b1 = s_b[1][d4], b2 = s_b[2][d4], b3 = s_b[3][d4];
        a.x += a1.x + a2.x + a3.x; a.y += a1.y + a2.y + a3.y;
        a.z += a1.z + a2.z + a3.z; a.w += a1.w + a2.w + a3.w;
        b.x += b1.x + b2.x + b3.x; b.y += b1.y + b2.y + b3.y;
        b.z += b1.z + b2.z + b3.z; b.w += b1.w + b2.w + b3.w;
        int d = d4 * 4;
        atomicAdd(&g_accA[d + 0], a.x); atomicAdd(&g_accA[d + 1], a.y);
        atomicAdd(&g_accA[d + 2], a.z); atomicAdd(&g_accA[d + 3], a.w);
        atomicAdd(&g_accB[d + 0], b.x); atomicAdd(&g_accB[d + 1], b.y);
        atomicAdd(&g_accB[d + 2], b.z); atomicAdd(&g_accB[d + 3], b.w);
    }
}

// ---------------- K6: logits + exp + block-aggregated sumexp ---------------------
// 1024 threads, 4 rows per warp -> 128 rows/block. Each block recomputes
// feat[256] (folds 1/sumw). |logits| tiny -> exp without max-shift exact.
__global__ void __launch_bounds__(1024)
k6_logits(const float* __restrict__ W, const float* __restrict__ b,
          float* __restrict__ out) {
    __shared__ float s_feat[D];
    __shared__ float s_p[32];
    int t = threadIdx.x;
    if (t < D) {
        float a  = 1.0f - (float)t * (1.0f / D);
        float be = 2.0f * (float)t * (1.0f / D) - 1.0f;
        float invS = 1.0f / g_sumw;
        s_feat[t] = (a * g_accA[t] + be * g_accB[t] + g_wte1[t]) * invS + g_qemb[t];
    }
    __syncthreads();
    int warp = t >> 5, lane = t & 31;
    int vbase = blockIdx.x * 128 + warp * 4;
    const float4* sf = (const float4*)s_feat;
    float4 f0 = sf[lane], f1 = sf[lane + 32];
    float s[4];
    #pragma unroll
    for (int r = 0; r < 4; ++r) {
        int v = vbase + r;
        s[r] = 0.0f;
        if (v < VOCAB) {
            const float4* row = (const float4*)(W + (size_t)v * D);
            float4 x0 = __ldg(&row[lane]);
            float4 x1 = __ldg(&row[lane + 32]);
            s[r] = dot8(x0, x1, f0, f1);
        }
    }
    #pragma unroll
    for (int r = 0; r < 4; ++r) s[r] = warp_sum(s[r]);
    float p_sum = 0.0f;
    if (lane == 0) {
        #pragma unroll
        for (int r = 0; r < 4; ++r) {
            int v = vbase + r;
            if (v < VOCAB) {
                float p = expf(s[r] + __ldg(&b[v]));
                out[v] = p;                  // unnormalized
                p_sum += p;
            }
        }
        s_p[warp] = p_sum;
    }
    __syncthreads();
    if (t < 32) {
        float x = s_p[t];
        x = warp_sum(x);
        if (t == 0) atomicAdd(&g_sumexp, x);
    }
}

// ---------------- K7: normalize output -------------------------------------------
__global__ void k7_scale(float* __restrict__ out) {
    int i = blockIdx.x * blockDim.x + threadIdx.x;
    float inv = 1.0f / g_sumexp;
    if (i < VOCAB) out[i] *= inv;
}

// ---------------- launch ---------------------------------------------------------
extern "C" void kernel_launch(void* const* d_in, const int* in_sizes, int n_in,
                              void* d_out, int out_size) {
    const int*   evidence = (const int*)  d_in[0];
    const int*   question = (const int*)  d_in[1];
    const float* q_table  = (const float*)d_in[2];
    const float* e_table  = (const float*)d_in[3];
    const float* te1      = (const float*)d_in[4];
    const float* te2      = (const float*)d_in[5];
    const float* W        = (const float*)d_in[6];
    const float* b        = (const float*)d_in[7];
    float* out = (float*)d_out;

    k1_qemb<<<1, 256>>>(question, q_table);
    k2_uw<<<VOCAB / 40, 256>>>(q_table);
    k34_weights<<<K34_BLOCKS, 256>>>(evidence, te2, te1);
    k5_etable<<<K5_BLOCKS, 256>>>(e_table);
    k6_logits<<<(VOCAB + 127) / 128, 1024>>>(W, b, out);
    k7_scale<<<(VOCAB + 255) / 256, 256>>>(out);
}

// round 8
// speedup vs baseline: 1.3395x; 1.2521x over previous
#include <cuda_runtime.h>
#include <cuda_bf16.h>

#define VOCAB 50000
#define D 256
#define E 20000
#define L 20

// ---------------- scratch (static device globals; no allocation) ----------------
__device__ float g_qemb[D];
__device__ float g_g0[D];        // alpha(d) * qemb[d]
__device__ float g_g1[D];        // beta(d)  * qemb[d]
__device__ float g_u[VOCAB];
__device__ float g_w[VOCAB];
__device__ float g_A[VOCAB];     // unnormalized attention mass per vocab id
__device__ float g_B[VOCAB];     // same, weighted by l/L
__device__ float g_accA[D];
__device__ float g_accB[D];
__device__ float g_wte1[D];
__device__ float g_sumw;         // sum of exp(scores)
__device__ float g_sumexp;       // sum of exp(logits)

__device__ __forceinline__ float warp_sum(float v) {
    #pragma unroll
    for (int o = 16; o > 0; o >>= 1) v += __shfl_xor_sync(0xffffffffu, v, o);
    return v;
}

__device__ __forceinline__ float dot8(float4 x0, float4 x1, float4 c0, float4 c1) {
    return x0.x*c0.x + x0.y*c0.y + x0.z*c0.z + x0.w*c0.w
         + x1.x*c1.x + x1.y*c1.y + x1.z*c1.z + x1.w*c1.w;
}

// cp.async helpers: MLP without registers
__device__ __forceinline__ void cp_async16(void* smem_dst, const void* gsrc) {
    unsigned sa = (unsigned)__cvta_generic_to_shared(smem_dst);
    asm volatile("cp.async.cg.shared.global [%0], [%1], 16;\n" :: "r"(sa), "l"(gsrc));
}
__device__ __forceinline__ void cp_commit() {
    asm volatile("cp.async.commit_group;\n");
}
template<int N> __device__ __forceinline__ void cp_wait() {
    asm volatile("cp.async.wait_group %0;\n" :: "n"(N));
}

#define TR      8                    // tile rows (8 x 256 floats = 8KB)
#define STAGES  3
#define NTILES  (VOCAB / TR)         // 6250
#define GRID_S  592                  // ~4 CTAs/SM

// ---------------- K1: q_emb + derived vectors, zero accumulators ----------------
__global__ void k1_qemb(const int* __restrict__ question,
                        const float* __restrict__ q_table) {
    int d = threadIdx.x;                         // 256 threads
    float a  = 1.0f - (float)d * (1.0f / D);
    float be = 2.0f * (float)d * (1.0f / D) - 1.0f;
    float s = 0.0f;
    #pragma unroll
    for (int l = 0; l < L; ++l) {
        int v = question[l];
        float pe = a + ((float)l * (1.0f / L)) * be;
        s += __ldg(&q_table[(size_t)v * D + d]) * pe;
    }
    g_qemb[d] = s;
    g_g0[d] = a * s;
    g_g1[d] = be * s;
    g_accA[d] = 0.0f; g_accB[d] = 0.0f; g_wte1[d] = 0.0f;
    if (d == 0) { g_sumw = 0.0f; g_sumexp = 0.0f; }
}

// ---------------- K2: u/w over q_table (cp.async pipeline); zero A/B -------------
__global__ void k2_uw(const float* __restrict__ q_table) {
    __shared__ __align__(16) float4 buf[STAGES][TR * 64];
    int t = threadIdx.x;                      // 256
    int warp = t >> 5, lane = t & 31;
    // zero A/B (strided over grid)
    for (int i = blockIdx.x * 256 + t; i < VOCAB; i += GRID_S * 256) {
        g_A[i] = 0.0f; g_B[i] = 0.0f;
    }
    // prologue: fill stages 0..STAGES-2
    #pragma unroll
    for (int s = 0; s < STAGES - 1; ++s) {
        int tt = blockIdx.x + s * GRID_S;
        if (tt < NTILES) {
            const float4* src = (const float4*)q_table + (size_t)tt * TR * 64;
            #pragma unroll
            for (int k = 0; k < 2; ++k)
                cp_async16(&buf[s][t + k * 256], src + t + k * 256);
        }
        cp_commit();
    }
    float4 c0 = ((const float4*)g_g0)[lane];
    float4 c1 = ((const float4*)g_g0)[lane + 32];
    float4 d0 = ((const float4*)g_g1)[lane];
    float4 d1 = ((const float4*)g_g1)[lane + 32];
    int stage = 0;
    for (int tile = blockIdx.x; tile < NTILES; tile += GRID_S) {
        cp_wait<STAGES - 2>();
        __syncthreads();
        float4 x0 = buf[stage][warp * 64 + lane];
        float4 x1 = buf[stage][warp * 64 + lane + 32];
        float u = dot8(x0, x1, c0, c1);
        float w = dot8(x0, x1, d0, d1);
        u = warp_sum(u); w = warp_sum(w);
        if (lane == 0) {
            int v = tile * TR + warp;
            g_u[v] = u; g_w[v] = w;
        }
        __syncthreads();
        int tt = tile + (STAGES - 1) * GRID_S;
        int fill = stage + (STAGES - 1); if (fill >= STAGES) fill -= STAGES;
        if (tt < NTILES) {
            const float4* src = (const float4*)q_table + (size_t)tt * TR * 64;
            #pragma unroll
            for (int k = 0; k < 2; ++k)
                cp_async16(&buf[fill][t + k * 256], src + t + k * 256);
        }
        cp_commit();
        stage = stage + 1; if (stage >= STAGES) stage = 0;
    }
}

// ---------------- K34: fused scores + exp + A/B scatter + weights@te1 ------------
#define K34_CHUNK  32
#define K34_BLOCKS (E / K34_CHUNK)    // 625
__global__ void k34_weights(const int* __restrict__ evidence,
                            const float* __restrict__ te2,
                            const float* __restrict__ te1) {
    __shared__ float4 sq[64];
    __shared__ float s_w[K34_CHUNK];
    int t = threadIdx.x;                      // 256
    int warp = t >> 5, lane = t & 31;
    if (t < 64) sq[t] = ((const float4*)g_qemb)[t];
    __syncthreads();
    int e0 = blockIdx.x * K34_CHUNK;
    float4 q0 = sq[lane], q1 = sq[lane + 32];
    float part[4];
    #pragma unroll
    for (int r = 0; r < 4; ++r) {
        int e = e0 + warp * 4 + r;
        float p = 0.0f;
        if (lane < L) {
            int v = __ldg(&evidence[e * L + lane]);
            p = g_u[v] + ((float)lane * (1.0f / L)) * g_w[v];
        }
        const float4* row = (const float4*)(te2 + (size_t)e * D);
        float4 x0 = __ldg(&row[lane]);
        float4 x1 = __ldg(&row[lane + 32]);
        part[r] = p + dot8(x0, x1, q0, q1);
    }
    #pragma unroll
    for (int r = 0; r < 4; ++r) part[r] = warp_sum(part[r]);
    if (lane == 0) {
        #pragma unroll
        for (int r = 0; r < 4; ++r) s_w[warp * 4 + r] = part[r];
    }
    __syncthreads();
    if (t < 32) {
        float w = expf(s_w[t]);
        s_w[t] = w;
        float s = warp_sum(w);
        if (t == 0) atomicAdd(&g_sumw, s);
    }
    __syncthreads();
    for (int i = t; i < K34_CHUNK * L; i += 256) {
        int el = i / L;
        int l  = i - el * L;
        int v  = __ldg(&evidence[(e0 + el) * L + l]);
        float w = s_w[el];
        atomicAdd(&g_A[v], w);
        atomicAdd(&g_B[v], w * ((float)l * (1.0f / L)));
    }
    int d = t;
    float acc = 0.0f;
    #pragma unroll 8
    for (int el = 0; el < K34_CHUNK; ++el)
        acc += s_w[el] * __ldg(&te1[(size_t)(e0 + el) * D + d]);
    atomicAdd(&g_wte1[d], acc);
}

// ---------------- K5: accA/accB = A@e_table, B@e_table (cp.async pipeline) -------
__global__ void k5_etable(const float* __restrict__ e_table) {
    __shared__ __align__(16) float4 buf[STAGES][TR * 64];
    __shared__ float4 s_a[4][64];
    __shared__ float4 s_b[4][64];
    int t = threadIdx.x;                      // 256
    int d4 = t & 63, r = t >> 6;              // column, row group 0..3
    #pragma unroll
    for (int s = 0; s < STAGES - 1; ++s) {
        int tt = blockIdx.x + s * GRID_S;
        if (tt < NTILES) {
            const float4* src = (const float4*)e_table + (size_t)tt * TR * 64;
            #pragma unroll
            for (int k = 0; k < 2; ++k)
                cp_async16(&buf[s][t + k * 256], src + t + k * 256);
        }
        cp_commit();
    }
    float4 a = make_float4(0.f, 0.f, 0.f, 0.f);
    float4 b = make_float4(0.f, 0.f, 0.f, 0.f);
    int stage = 0;
    for (int tile = blockIdx.x; tile < NTILES; tile += GRID_S) {
        float Av0 = __ldg(&g_A[tile * TR + r]);
        float Bv0 = __ldg(&g_B[tile * TR + r]);
        float Av1 = __ldg(&g_A[tile * TR + 4 + r]);
        float Bv1 = __ldg(&g_B[tile * TR + 4 + r]);
        cp_wait<STAGES - 2>();
        __syncthreads();
        float4 x0 = buf[stage][r * 64 + d4];
        float4 x1 = buf[stage][(4 + r) * 64 + d4];
        a.x += Av0 * x0.x + Av1 * x1.x; a.y += Av0 * x0.y + Av1 * x1.y;
        a.z += Av0 * x0.z + Av1 * x1.z; a.w += Av0 * x0.w + Av1 * x1.w;
        b.x += Bv0 * x0.x + Bv1 * x1.x; b.y += Bv0 * x0.y + Bv1 * x1.y;
        b.z += Bv0 * x0.z + Bv1 * x1.z; b.w += Bv0 * x0.w + Bv1 * x1.w;
        __syncthreads();
        int tt = tile + (STAGES - 1) * GRID_S;
        int fill = stage + (STAGES - 1); if (fill >= STAGES) fill -= STAGES;
        if (tt < NTILES) {
            const float4* src = (const float4*)e_table + (size_t)tt * TR * 64;
            #pragma unroll
            for (int k = 0; k < 2; ++k)
                cp_async16(&buf[fill][t + k * 256], src + t + k * 256);
        }
        cp_commit();
        stage = stage + 1; if (stage >= STAGES) stage = 0;
    }
    s_a[r][d4] = a; s_b[r][d4] = b;
    __syncthreads();
    if (r == 0) {
        float4 a1 = s_a[1][d4], a2 = s_a[2][d4], a3 = s_a[3][d4];
        float4 b1 = s_b[1][d4], b2 = s_b[2][d4], b3 = s_b[3][d4];
        a.x += a1.x + a2.x + a3.x; a.y += a1.y + a2.y + a3.y;
        a.z += a1.z + a2.z + a3.z; a.w += a1.w + a2.w + a3.w;
        b.x += b1.x + b2.x + b3.x; b.y += b1.y + b2.y + b3.y;
        b.z += b1.z + b2.z + b3.z; b.w += b1.w + b2.w + b3.w;
        int d = d4 * 4;
        atomicAdd(&g_accA[d + 0], a.x); atomicAdd(&g_accA[d + 1], a.y);
        atomicAdd(&g_accA[d + 2], a.z); atomicAdd(&g_accA[d + 3], a.w);
        atomicAdd(&g_accB[d + 0], b.x); atomicAdd(&g_accB[d + 1], b.y);
        atomicAdd(&g_accB[d + 2], b.z); atomicAdd(&g_accB[d + 3], b.w);
    }
}

// ---------------- K6: logits + exp + sumexp (cp.async pipeline over W) -----------
__global__ void k6_logits(const float* __restrict__ W, const float* __restrict__ b,
                          float* __restrict__ out) {
    __shared__ __align__(16) float4 buf[STAGES][TR * 64];
    __shared__ float s_feat[D];
    __shared__ float s_p[8];
    int t = threadIdx.x;                      // 256
    int warp = t >> 5, lane = t & 31;
    #pragma unroll
    for (int s = 0; s < STAGES - 1; ++s) {
        int tt = blockIdx.x + s * GRID_S;
        if (tt < NTILES) {
            const float4* src = (const float4*)W + (size_t)tt * TR * 64;
            #pragma unroll
            for (int k = 0; k < 2; ++k)
                cp_async16(&buf[s][t + k * 256], src + t + k * 256);
        }
        cp_commit();
    }
    {
        float a  = 1.0f - (float)t * (1.0f / D);
        float be = 2.0f * (float)t * (1.0f / D) - 1.0f;
        float invS = 1.0f / g_sumw;
        s_feat[t] = (a * g_accA[t] + be * g_accB[t] + g_wte1[t]) * invS + g_qemb[t];
    }
    __syncthreads();
    const float4* sf = (const float4*)s_feat;
    float4 f0 = sf[lane], f1 = sf[lane + 32];
    float p_sum = 0.0f;
    int stage = 0;
    for (int tile = blockIdx.x; tile < NTILES; tile += GRID_S) {
        int v = tile * TR + warp;
        float bias = (lane == 0) ? __ldg(&b[v]) : 0.0f;  // overlaps cp wait
        cp_wait<STAGES - 2>();
        __syncthreads();
        float4 x0 = buf[stage][warp * 64 + lane];
        float4 x1 = buf[stage][warp * 64 + lane + 32];
        float s = dot8(x0, x1, f0, f1);
        s = warp_sum(s);
        if (lane == 0) {
            float p = expf(s + bias);
            out[v] = p;                       // unnormalized
            p_sum += p;
        }
        __syncthreads();
        int tt = tile + (STAGES - 1) * GRID_S;
        int fill = stage + (STAGES - 1); if (fill >= STAGES) fill -= STAGES;
        if (tt < NTILES) {
            const float4* src = (const float4*)W + (size_t)tt * TR * 64;
            #pragma unroll
            for (int k = 0; k < 2; ++k)
                cp_async16(&buf[fill][t + k * 256], src + t + k * 256);
        }
        cp_commit();
        stage = stage + 1; if (stage >= STAGES) stage = 0;
    }
    if (lane == 0) s_p[warp] = p_sum;
    __syncthreads();
    if (t < 8) {
        float x = s_p[t];
        #pragma unroll
        for (int o = 4; o > 0; o >>= 1) x += __shfl_xor_sync(0xffu, x, o);
        if (t == 0) atomicAdd(&g_sumexp, x);
    }
}

// ---------------- K7: normalize output -------------------------------------------
__global__ void k7_scale(float* __restrict__ out) {
    int i = blockIdx.x * blockDim.x + threadIdx.x;
    float inv = 1.0f / g_sumexp;
    if (i < VOCAB) out[i] *= inv;
}

// ---------------- launch ---------------------------------------------------------
extern "C" void kernel_launch(void* const* d_in, const int* in_sizes, int n_in,
                              void* d_out, int out_size) {
    const int*   evidence = (const int*)  d_in[0];
    const int*   question = (const int*)  d_in[1];
    const float* q_table  = (const float*)d_in[2];
    const float* e_table  = (const float*)d_in[3];
    const float* te1      = (const float*)d_in[4];
    const float* te2      = (const float*)d_in[5];
    const float* W        = (const float*)d_in[6];
    const float* b        = (const float*)d_in[7];
    float* out = (float*)d_out;

    k1_qemb<<<1, 256>>>(question, q_table);
    k2_uw<<<GRID_S, 256>>>(q_table);
    k34_weights<<<K34_BLOCKS, 256>>>(evidence, te2, te1);
    k5_etable<<<GRID_S, 256>>>(e_table);
    k6_logits<<<GRID_S, 256>>>(W, b, out);
    k7_scale<<<(VOCAB + 255) / 256, 256>>>(out);
}

// round 9
// speedup vs baseline: 1.5883x; 1.1858x over previous
#include <cuda_runtime.h>
#include <cuda_bf16.h>

#define VOCAB 50000
#define D 256
#define E 20000
#define L 20

// ---------------- scratch (static device globals; no allocation) ----------------
__device__ float g_qemb[D];
__device__ float g_g0[D];        // alpha(d) * qemb[d]
__device__ float g_g1[D];        // beta(d)  * qemb[d]
__device__ float g_u[VOCAB];
__device__ float g_w[VOCAB];
__device__ float g_A[VOCAB];     // unnormalized attention mass per vocab id
__device__ float g_B[VOCAB];     // same, weighted by l/L
__device__ float g_accA[D];
__device__ float g_accB[D];
__device__ float g_wte1[D];
__device__ float g_sumw;         // sum of exp(scores)
__device__ float g_sumexp;       // sum of exp(logits)

__device__ __forceinline__ float warp_sum(float v) {
    #pragma unroll
    for (int o = 16; o > 0; o >>= 1) v += __shfl_xor_sync(0xffffffffu, v, o);
    return v;
}

__device__ __forceinline__ float dot8(float4 x0, float4 x1, float4 c0, float4 c1) {
    return x0.x*c0.x + x0.y*c0.y + x0.z*c0.z + x0.w*c0.w
         + x1.x*c1.x + x1.y*c1.y + x1.z*c1.z + x1.w*c1.w;
}

// ---------------- K1: q_emb + derived vectors, zero accumulators ----------------
__global__ void k1_qemb(const int* __restrict__ question,
                        const float* __restrict__ q_table) {
    int d = threadIdx.x;                         // 256 threads
    float a  = 1.0f - (float)d * (1.0f / D);
    float be = 2.0f * (float)d * (1.0f / D) - 1.0f;
    float s = 0.0f;
    #pragma unroll
    for (int l = 0; l < L; ++l) {
        int v = question[l];
        float pe = a + ((float)l * (1.0f / L)) * be;
        s += __ldg(&q_table[(size_t)v * D + d]) * pe;
    }
    g_qemb[d] = s;
    g_g0[d] = a * s;
    g_g1[d] = be * s;
    g_accA[d] = 0.0f; g_accB[d] = 0.0f; g_wte1[d] = 0.0f;
    if (d == 0) { g_sumw = 0.0f; g_sumexp = 0.0f; }
}

// ---------------- K2: u[v], w[v] over q_table; zero A/B --------------------------
// 2 rows per warp, 16 rows/block, grid 3125. 4 independent LDG.128 per thread.
__global__ void k2_uw(const float* __restrict__ q_table) {
    __shared__ float4 s0[64], s1[64];
    int t = threadIdx.x;                      // 256
    if (t < 64) {
        s0[t] = ((const float4*)g_g0)[t];
        s1[t] = ((const float4*)g_g1)[t];
    }
    __syncthreads();
    int warp = t >> 5, lane = t & 31;
    int vbase = blockIdx.x * 16 + warp * 2;
    const float4* rowA = (const float4*)(q_table + (size_t)vbase * D);
    const float4* rowB = (const float4*)(q_table + (size_t)(vbase + 1) * D);
    float4 xa0 = __ldg(&rowA[lane]);
    float4 xa1 = __ldg(&rowA[lane + 32]);
    float4 xb0 = __ldg(&rowB[lane]);
    float4 xb1 = __ldg(&rowB[lane + 32]);
    float4 c0 = s0[lane], c1 = s0[lane + 32];
    float4 d0 = s1[lane], d1 = s1[lane + 32];
    float u0 = dot8(xa0, xa1, c0, c1);
    float w0 = dot8(xa0, xa1, d0, d1);
    float u1 = dot8(xb0, xb1, c0, c1);
    float w1 = dot8(xb0, xb1, d0, d1);
    u0 = warp_sum(u0); w0 = warp_sum(w0);
    u1 = warp_sum(u1); w1 = warp_sum(w1);
    if (lane == 0) {
        g_u[vbase] = u0;     g_w[vbase] = w0;
        g_u[vbase + 1] = u1; g_w[vbase + 1] = w1;
    }
    if (t < 16) { g_A[blockIdx.x * 16 + t] = 0.0f; g_B[blockIdx.x * 16 + t] = 0.0f; }
}

// ---------------- K34: fused scores + exp + A/B scatter + weights@te1 ------------
// (round-4 proven config: chunk 32, 625 blocks)
#define K34_CHUNK  32
#define K34_BLOCKS (E / K34_CHUNK)    // 625
__global__ void k34_weights(const int* __restrict__ evidence,
                            const float* __restrict__ te2,
                            const float* __restrict__ te1) {
    __shared__ float4 sq[64];
    __shared__ float s_w[K34_CHUNK];
    int t = threadIdx.x;                      // 256
    int warp = t >> 5, lane = t & 31;
    if (t < 64) sq[t] = ((const float4*)g_qemb)[t];
    __syncthreads();
    int e0 = blockIdx.x * K34_CHUNK;
    float4 q0 = sq[lane], q1 = sq[lane + 32];
    float part[4];
    #pragma unroll
    for (int r = 0; r < 4; ++r) {
        int e = e0 + warp * 4 + r;
        float p = 0.0f;
        if (lane < L) {
            int v = __ldg(&evidence[e * L + lane]);
            p = g_u[v] + ((float)lane * (1.0f / L)) * g_w[v];
        }
        const float4* row = (const float4*)(te2 + (size_t)e * D);
        float4 x0 = __ldg(&row[lane]);
        float4 x1 = __ldg(&row[lane + 32]);
        part[r] = p + dot8(x0, x1, q0, q1);
    }
    #pragma unroll
    for (int r = 0; r < 4; ++r) part[r] = warp_sum(part[r]);
    if (lane == 0) {
        #pragma unroll
        for (int r = 0; r < 4; ++r) s_w[warp * 4 + r] = part[r];
    }
    __syncthreads();
    if (t < 32) {
        float w = expf(s_w[t]);
        s_w[t] = w;
        float s = warp_sum(w);
        if (t == 0) atomicAdd(&g_sumw, s);
    }
    __syncthreads();
    for (int i = t; i < K34_CHUNK * L; i += 256) {
        int el = i / L;
        int l  = i - el * L;
        int v  = __ldg(&evidence[(e0 + el) * L + l]);
        float w = s_w[el];
        atomicAdd(&g_A[v], w);
        atomicAdd(&g_B[v], w * ((float)l * (1.0f / L)));
    }
    int d = t;
    float acc = 0.0f;
    #pragma unroll 8
    for (int el = 0; el < K34_CHUNK; ++el)
        acc += s_w[el] * __ldg(&te1[(size_t)(e0 + el) * D + d]);
    atomicAdd(&g_wte1[d], acc);
}

// ---------------- K5: accA/accB = A@e_table, B@e_table ---------------------------
// grid-stride, 4 rows per iteration, thread = column. 4 independent scalar LDG
// per iteration + broadcast A/B loads. Low regs -> max occupancy (8 CTAs/SM).
#define K5_GRID 1184
__global__ void k5_etable(const float* __restrict__ e_table) {
    int t = threadIdx.x;                      // 256 (= column)
    float a = 0.0f, b = 0.0f;
    const int nquads = VOCAB / 4;             // 12500
    for (int q = blockIdx.x; q < nquads; q += K5_GRID) {
        int v = q * 4;
        float x0 = __ldg(&e_table[(size_t)(v + 0) * D + t]);
        float x1 = __ldg(&e_table[(size_t)(v + 1) * D + t]);
        float x2 = __ldg(&e_table[(size_t)(v + 2) * D + t]);
        float x3 = __ldg(&e_table[(size_t)(v + 3) * D + t]);
        float A0 = __ldg(&g_A[v + 0]), A1 = __ldg(&g_A[v + 1]);
        float A2 = __ldg(&g_A[v + 2]), A3 = __ldg(&g_A[v + 3]);
        float B0 = __ldg(&g_B[v + 0]), B1 = __ldg(&g_B[v + 1]);
        float B2 = __ldg(&g_B[v + 2]), B3 = __ldg(&g_B[v + 3]);
        a += A0 * x0 + A1 * x1 + A2 * x2 + A3 * x3;
        b += B0 * x0 + B1 * x1 + B2 * x2 + B3 * x3;
    }
    atomicAdd(&g_accA[t], a);
    atomicAdd(&g_accB[t], b);
}

// ---------------- K6: logits + exp + block-aggregated sumexp ---------------------
// 2 rows per warp, 16 rows/block, grid 3125. Block recomputes feat[256]
// (folds 1/sumw). |logits| tiny -> exp without max-shift exact.
__global__ void k6_logits(const float* __restrict__ W, const float* __restrict__ b,
                          float* __restrict__ out) {
    __shared__ float s_feat[D];
    __shared__ float s_p[8];
    int t = threadIdx.x;                      // 256
    {
        float a  = 1.0f - (float)t * (1.0f / D);
        float be = 2.0f * (float)t * (1.0f / D) - 1.0f;
        float invS = 1.0f / g_sumw;
        s_feat[t] = (a * g_accA[t] + be * g_accB[t] + g_wte1[t]) * invS + g_qemb[t];
    }
    __syncthreads();
    int warp = t >> 5, lane = t & 31;
    int vbase = blockIdx.x * 16 + warp * 2;
    const float4* rowA = (const float4*)(W + (size_t)vbase * D);
    const float4* rowB = (const float4*)(W + (size_t)(vbase + 1) * D);
    float4 xa0 = __ldg(&rowA[lane]);
    float4 xa1 = __ldg(&rowA[lane + 32]);
    float4 xb0 = __ldg(&rowB[lane]);
    float4 xb1 = __ldg(&rowB[lane + 32]);
    const float4* sf = (const float4*)s_feat;
    float4 f0 = sf[lane], f1 = sf[lane + 32];
    float s0 = dot8(xa0, xa1, f0, f1);
    float s1 = dot8(xb0, xb1, f0, f1);
    s0 = warp_sum(s0); s1 = warp_sum(s1);
    float p_sum = 0.0f;
    if (lane == 0) {
        float p0 = expf(s0 + __ldg(&b[vbase]));
        float p1 = expf(s1 + __ldg(&b[vbase + 1]));
        out[vbase] = p0;                      // unnormalized
        out[vbase + 1] = p1;
        p_sum = p0 + p1;
        s_p[warp] = p_sum;
    }
    __syncthreads();
    if (t < 8) {
        float x = s_p[t];
        #pragma unroll
        for (int o = 4; o > 0; o >>= 1) x += __shfl_xor_sync(0xffu, x, o);
        if (t == 0) atomicAdd(&g_sumexp, x);
    }
}

// ---------------- K7: normalize output -------------------------------------------
__global__ void k7_scale(float* __restrict__ out) {
    int i = blockIdx.x * blockDim.x + threadIdx.x;
    float inv = 1.0f / g_sumexp;
    if (i < VOCAB) out[i] *= inv;
}

// ---------------- launch ---------------------------------------------------------
extern "C" void kernel_launch(void* const* d_in, const int* in_sizes, int n_in,
                              void* d_out, int out_size) {
    const int*   evidence = (const int*)  d_in[0];
    const int*   question = (const int*)  d_in[1];
    const float* q_table  = (const float*)d_in[2];
    const float* e_table  = (const float*)d_in[3];
    const float* te1      = (const float*)d_in[4];
    const float* te2      = (const float*)d_in[5];
    const float* W        = (const float*)d_in[6];
    const float* b        = (const float*)d_in[7];
    float* out = (float*)d_out;

    k1_qemb<<<1, 256>>>(question, q_table);
    k2_uw<<<VOCAB / 16, 256>>>(q_table);
    k34_weights<<<K34_BLOCKS, 256>>>(evidence, te2, te1);
    k5_etable<<<K5_GRID, 256>>>(e_table);
    k6_logits<<<VOCAB / 16, 256>>>(W, b, out);
    k7_scale<<<(VOCAB + 255) / 256, 256>>>(out);
}

// round 10
// speedup vs baseline: 1.6860x; 1.0615x over previous
#include <cuda_runtime.h>
#include <cuda_bf16.h>

#define VOCAB 50000
#define D 256
#define E 20000
#define L 20

// ---------------- scratch (static device globals; no allocation) ----------------
__device__ float g_qemb[D];
__device__ float g_g0[D];        // alpha(d) * qemb[d]
__device__ float g_g1[D];        // beta(d)  * qemb[d]
__device__ float g_u[VOCAB];
__device__ float g_w[VOCAB];
__device__ __align__(16) float g_A[VOCAB];  // unnormalized attention mass per vocab id
__device__ __align__(16) float g_B[VOCAB];  // same, weighted by l/L
__device__ float g_accA[D];
__device__ float g_accB[D];
__device__ float g_wte1[D];
__device__ float g_sumw;         // sum of exp(scores)
__device__ float g_sumexp;       // sum of exp(logits)

__device__ __forceinline__ float warp_sum(float v) {
    #pragma unroll
    for (int o = 16; o > 0; o >>= 1) v += __shfl_xor_sync(0xffffffffu, v, o);
    return v;
}

__device__ __forceinline__ float dot8(float4 x0, float4 x1, float4 c0, float4 c1) {
    return x0.x*c0.x + x0.y*c0.y + x0.z*c0.z + x0.w*c0.w
         + x1.x*c1.x + x1.y*c1.y + x1.z*c1.z + x1.w*c1.w;
}

// ---------------- K1: q_emb + derived vectors, zero accumulators ----------------
__global__ void k1_qemb(const int* __restrict__ question,
                        const float* __restrict__ q_table) {
    int d = threadIdx.x;                         // 256 threads
    float a  = 1.0f - (float)d * (1.0f / D);
    float be = 2.0f * (float)d * (1.0f / D) - 1.0f;
    float s = 0.0f;
    #pragma unroll
    for (int l = 0; l < L; ++l) {
        int v = question[l];
        float pe = a + ((float)l * (1.0f / L)) * be;
        s += __ldg(&q_table[(size_t)v * D + d]) * pe;
    }
    g_qemb[d] = s;
    g_g0[d] = a * s;
    g_g1[d] = be * s;
    g_accA[d] = 0.0f; g_accB[d] = 0.0f; g_wte1[d] = 0.0f;
    if (d == 0) { g_sumw = 0.0f; g_sumexp = 0.0f; }
}

// ---------------- K2: u[v], w[v] over q_table; zero A/B --------------------------
// 2 rows per warp, 16 rows/block, grid 3125. 4 independent LDG.128 per thread.
__global__ void k2_uw(const float* __restrict__ q_table) {
    __shared__ float4 s0[64], s1[64];
    int t = threadIdx.x;                      // 256
    if (t < 64) {
        s0[t] = ((const float4*)g_g0)[t];
        s1[t] = ((const float4*)g_g1)[t];
    }
    __syncthreads();
    int warp = t >> 5, lane = t & 31;
    int vbase = blockIdx.x * 16 + warp * 2;
    const float4* rowA = (const float4*)(q_table + (size_t)vbase * D);
    const float4* rowB = (const float4*)(q_table + (size_t)(vbase + 1) * D);
    float4 xa0 = __ldg(&rowA[lane]);
    float4 xa1 = __ldg(&rowA[lane + 32]);
    float4 xb0 = __ldg(&rowB[lane]);
    float4 xb1 = __ldg(&rowB[lane + 32]);
    float4 c0 = s0[lane], c1 = s0[lane + 32];
    float4 d0 = s1[lane], d1 = s1[lane + 32];
    float u0 = dot8(xa0, xa1, c0, c1);
    float w0 = dot8(xa0, xa1, d0, d1);
    float u1 = dot8(xb0, xb1, c0, c1);
    float w1 = dot8(xb0, xb1, d0, d1);
    u0 = warp_sum(u0); w0 = warp_sum(w0);
    u1 = warp_sum(u1); w1 = warp_sum(w1);
    if (lane == 0) {
        g_u[vbase] = u0;     g_w[vbase] = w0;
        g_u[vbase + 1] = u1; g_w[vbase + 1] = w1;
    }
    if (t < 16) { g_A[blockIdx.x * 16 + t] = 0.0f; g_B[blockIdx.x * 16 + t] = 0.0f; }
}

// ---------------- K34: fused scores + exp + A/B scatter + weights@te1 ------------
#define K34_CHUNK  32
#define K34_BLOCKS (E / K34_CHUNK)    // 625
__global__ void k34_weights(const int* __restrict__ evidence,
                            const float* __restrict__ te2,
                            const float* __restrict__ te1) {
    __shared__ float4 sq[64];
    __shared__ float s_w[K34_CHUNK];
    int t = threadIdx.x;                      // 256
    int warp = t >> 5, lane = t & 31;
    if (t < 64) sq[t] = ((const float4*)g_qemb)[t];
    __syncthreads();
    int e0 = blockIdx.x * K34_CHUNK;
    float4 q0 = sq[lane], q1 = sq[lane + 32];
    float part[4];
    #pragma unroll
    for (int r = 0; r < 4; ++r) {
        int e = e0 + warp * 4 + r;
        float p = 0.0f;
        if (lane < L) {
            int v = __ldg(&evidence[e * L + lane]);
            p = g_u[v] + ((float)lane * (1.0f / L)) * g_w[v];
        }
        const float4* row = (const float4*)(te2 + (size_t)e * D);
        float4 x0 = __ldg(&row[lane]);
        float4 x1 = __ldg(&row[lane + 32]);
        part[r] = p + dot8(x0, x1, q0, q1);
    }
    #pragma unroll
    for (int r = 0; r < 4; ++r) part[r] = warp_sum(part[r]);
    if (lane == 0) {
        #pragma unroll
        for (int r = 0; r < 4; ++r) s_w[warp * 4 + r] = part[r];
    }
    __syncthreads();
    if (t < 32) {
        float w = expf(s_w[t]);
        s_w[t] = w;
        float s = warp_sum(w);
        if (t == 0) atomicAdd(&g_sumw, s);
    }
    __syncthreads();
    for (int i = t; i < K34_CHUNK * L; i += 256) {
        int el = i / L;
        int l  = i - el * L;
        int v  = __ldg(&evidence[(e0 + el) * L + l]);
        float w = s_w[el];
        atomicAdd(&g_A[v], w);
        atomicAdd(&g_B[v], w * ((float)l * (1.0f / L)));
    }
    int d = t;
    float acc = 0.0f;
    #pragma unroll 8
    for (int el = 0; el < K34_CHUNK; ++el)
        acc += s_w[el] * __ldg(&te1[(size_t)(e0 + el) * D + d]);
    atomicAdd(&g_wte1[d], acc);
}

// ---------------- K5: accA/accB = A@e_table, B@e_table ---------------------------
// grid-stride, 8 rows per iteration, thread = column. 8 independent stream LDG
// + 4 uniform float4 A/B loads per iter (12 LDG per KB vs 24 before).
#define K5_GRID 1184
__global__ void k5_etable(const float* __restrict__ e_table) {
    int t = threadIdx.x;                      // 256 (= column)
    float a = 0.0f, b = 0.0f;
    const int nocts = VOCAB / 8;              // 6250
    for (int q = blockIdx.x; q < nocts; q += K5_GRID) {
        int v = q * 8;
        const float* base = e_table + (size_t)v * D + t;
        float x0 = __ldg(base + 0 * D);
        float x1 = __ldg(base + 1 * D);
        float x2 = __ldg(base + 2 * D);
        float x3 = __ldg(base + 3 * D);
        float x4 = __ldg(base + 4 * D);
        float x5 = __ldg(base + 5 * D);
        float x6 = __ldg(base + 6 * D);
        float x7 = __ldg(base + 7 * D);
        float4 A0 = __ldg((const float4*)&g_A[v]);
        float4 A1 = __ldg((const float4*)&g_A[v + 4]);
        float4 B0 = __ldg((const float4*)&g_B[v]);
        float4 B1 = __ldg((const float4*)&g_B[v + 4]);
        a += A0.x * x0 + A0.y * x1 + A0.z * x2 + A0.w * x3
           + A1.x * x4 + A1.y * x5 + A1.z * x6 + A1.w * x7;
        b += B0.x * x0 + B0.y * x1 + B0.z * x2 + B0.w * x3
           + B1.x * x4 + B1.y * x5 + B1.z * x6 + B1.w * x7;
    }
    atomicAdd(&g_accA[t], a);
    atomicAdd(&g_accB[t], b);
}

// ---------------- K6: logits + exp + block-aggregated sumexp ---------------------
// 2 rows per warp, 16 rows/block, grid 3125. Block recomputes feat[256]
// (folds 1/sumw). |logits| tiny -> exp without max-shift exact.
__global__ void k6_logits(const float* __restrict__ W, const float* __restrict__ b,
                          float* __restrict__ out) {
    __shared__ float s_feat[D];
    __shared__ float s_p[8];
    int t = threadIdx.x;                      // 256
    {
        float a  = 1.0f - (float)t * (1.0f / D);
        float be = 2.0f * (float)t * (1.0f / D) - 1.0f;
        float invS = 1.0f / g_sumw;
        s_feat[t] = (a * g_accA[t] + be * g_accB[t] + g_wte1[t]) * invS + g_qemb[t];
    }
    __syncthreads();
    int warp = t >> 5, lane = t & 31;
    int vbase = blockIdx.x * 16 + warp * 2;
    const float4* rowA = (const float4*)(W + (size_t)vbase * D);
    const float4* rowB = (const float4*)(W + (size_t)(vbase + 1) * D);
    float4 xa0 = __ldg(&rowA[lane]);
    float4 xa1 = __ldg(&rowA[lane + 32]);
    float4 xb0 = __ldg(&rowB[lane]);
    float4 xb1 = __ldg(&rowB[lane + 32]);
    const float4* sf = (const float4*)s_feat;
    float4 f0 = sf[lane], f1 = sf[lane + 32];
    float s0 = dot8(xa0, xa1, f0, f1);
    float s1 = dot8(xb0, xb1, f0, f1);
    s0 = warp_sum(s0); s1 = warp_sum(s1);
    float p_sum = 0.0f;
    if (lane == 0) {
        float p0 = expf(s0 + __ldg(&b[vbase]));
        float p1 = expf(s1 + __ldg(&b[vbase + 1]));
        out[vbase] = p0;                      // unnormalized
        out[vbase + 1] = p1;
        p_sum = p0 + p1;
        s_p[warp] = p_sum;
    }
    __syncthreads();
    if (t < 8) {
        float x = s_p[t];
        #pragma unroll
        for (int o = 4; o > 0; o >>= 1) x += __shfl_xor_sync(0xffu, x, o);
        if (t == 0) atomicAdd(&g_sumexp, x);
    }
}

// ---------------- K7: normalize output -------------------------------------------
__global__ void k7_scale(float* __restrict__ out) {
    int i = blockIdx.x * blockDim.x + threadIdx.x;
    float inv = 1.0f / g_sumexp;
    if (i < VOCAB) out[i] *= inv;
}

// ---------------- launch ---------------------------------------------------------
extern "C" void kernel_launch(void* const* d_in, const int* in_sizes, int n_in,
                              void* d_out, int out_size) {
    const int*   evidence = (const int*)  d_in[0];
    const int*   question = (const int*)  d_in[1];
    const float* q_table  = (const float*)d_in[2];
    const float* e_table  = (const float*)d_in[3];
    const float* te1      = (const float*)d_in[4];
    const float* te2      = (const float*)d_in[5];
    const float* W        = (const float*)d_in[6];
    const float* b        = (const float*)d_in[7];
    float* out = (float*)d_out;

    k1_qemb<<<1, 256>>>(question, q_table);
    k2_uw<<<VOCAB / 16, 256>>>(q_table);
    k34_weights<<<K34_BLOCKS, 256>>>(evidence, te2, te1);
    k5_etable<<<K5_GRID, 256>>>(e_table);
    k6_logits<<<VOCAB / 16, 256>>>(W, b, out);
    k7_scale<<<(VOCAB + 255) / 256, 256>>>(out);
}